// round 7
// baseline (speedup 1.0000x reference)
#include <cuda_runtime.h>
#include <math.h>

#define RCR 5.2f
#define RCA 3.5f
#define NSP 4
#define NATOMS 32
#define NSHFR 16
#define NSHFA 4
#define NSHFZ 8
#define NPAIRBIN 10
#define RAD_FEAT (NSP*NSHFR)            /* 64  */
#define ANG_FEAT (NPAIRBIN*NSHFA*NSHFZ) /* 320 */
#define OUT_FEAT (RAD_FEAT+ANG_FEAT)    /* 384 */
#define AWARPS 4
#define MAXP 480                         /* 31*30/2=465 + <=10 pads, even */
#define LOG2E 1.4426950408889634f
#define SQRT095 0.97467943448089633f

typedef unsigned long long ull;

__device__ __forceinline__ float ex2f(float x){ float y; asm("ex2.approx.ftz.f32 %0, %1;":"=f"(y):"f"(x)); return y; }
__device__ __forceinline__ float lg2f(float x){ float y; asm("lg2.approx.ftz.f32 %0, %1;":"=f"(y):"f"(x)); return y; }
__device__ __forceinline__ float sqrt_apx(float x){ float y; asm("sqrt.approx.ftz.f32 %0, %1;":"=f"(y):"f"(x)); return y; }
__device__ __forceinline__ float rsqrt_apx(float x){ float y; asm("rsqrt.approx.ftz.f32 %0, %1;":"=f"(y):"f"(x)); return y; }

__device__ __forceinline__ ull pk2(float lo, float hi){ ull r; asm("mov.b64 %0,{%1,%2};":"=l"(r):"f"(lo),"f"(hi)); return r; }
__device__ __forceinline__ void upk2(ull v, float& lo, float& hi){ asm("mov.b64 {%0,%1},%2;":"=f"(lo),"=f"(hi):"l"(v)); }
__device__ __forceinline__ ull fma2(ull a, ull b, ull c){ ull d; asm("fma.rn.f32x2 %0,%1,%2,%3;":"=l"(d):"l"(a),"l"(b),"l"(c)); return d; }
__device__ __forceinline__ ull mul2(ull a, ull b){ ull d; asm("mul.rn.f32x2 %0,%1,%2;":"=l"(d):"l"(a),"l"(b)); return d; }
__device__ __forceinline__ ull add2(ull a, ull b){ ull d; asm("add.rn.f32x2 %0,%1,%2;":"=l"(d):"l"(a),"l"(b)); return d; }

__global__ __launch_bounds__(AWARPS*32) void aev_kernel(
    const float* __restrict__ coords,
    const float* __restrict__ etaR_p,
    const float* __restrict__ shfR_p,
    const float* __restrict__ etaA_p,
    const float* __restrict__ zeta_p,
    const float* __restrict__ shfA_p,
    const float* __restrict__ shfZ_p,
    const int*   __restrict__ species,
    float* __restrict__ out)
{
    __shared__ float s_cx[NATOMS], s_cy[NATOMS], s_cz[NATOMS];
    __shared__ int   s_sp[NATOMS];
    __shared__ float s_shfR[NSHFR], s_shfA[NSHFA];
    __shared__ float s_cosZ[NSHFZ], s_sinZ[NSHFZ];
    __shared__ float4 s_n4[NATOMS];          // ux,uy,uz (x sqrt095), 0.5*d
    __shared__ float  s_nlg[NATOMS];         // lg2(fcA)
    __shared__ int    s_nsp[NATOMS];         // species
    __shared__ __align__(8) float s_c [MAXP];   // SoA pair records (bin-sorted)
    __shared__ __align__(8) float s_s [MAXP];
    __shared__ __align__(8) float s_A [MAXP];
    __shared__ __align__(8) float s_B [MAXP];
    __shared__ int    s_pos[NPAIRBIN];       // fill cursors
    __shared__ float  s_acc[AWARPS][OUT_FEAT];
    __shared__ float  s_etaR, s_etaA, s_zeta;

    const int tid  = threadIdx.x;
    const int w    = tid >> 5;
    const int lane = tid & 31;
    const int b    = blockIdx.x >> 5;        // 32 blocks per molecule
    const int i    = blockIdx.x & 31;        // this block's atom

    // ---- block-wide loads ----
    if (tid < NATOMS) {
        s_cx[tid] = coords[(b*NATOMS + tid)*3 + 0];
        s_cy[tid] = coords[(b*NATOMS + tid)*3 + 1];
        s_cz[tid] = coords[(b*NATOMS + tid)*3 + 2];
        s_sp[tid] = species[b*NATOMS + tid];
    } else if (tid < 32 + NSHFR) {
        s_shfR[tid-32] = shfR_p[tid-32];
    } else if (tid < 48 + NSHFA) {
        s_shfA[tid-48] = shfA_p[tid-48];
    } else if (tid < 55) {
        if (tid == 52) s_etaR = etaR_p[0];
        if (tid == 53) s_etaA = etaA_p[0];
        if (tid == 54) s_zeta = zeta_p[0];
    } else if (tid >= 56 && tid < 64) {
        float z = shfZ_p[tid-56];
        s_cosZ[tid-56] = cosf(z);
        s_sinZ[tid-56] = sinf(z);
    }
    for (int f = tid; f < AWARPS*OUT_FEAT; f += blockDim.x)
        (&s_acc[0][0])[f] = 0.0f;
    __syncthreads();

    const float zeta = s_zeta;
    const float nEtaR = -s_etaR * LOG2E;
    const float nEtaA = -s_etaA * LOG2E;
    const bool  z32   = (fabsf(zeta - 32.0f) < 1e-4f);
    const float PI_RCR = 3.14159265358979323846f / RCR;
    const float PI_RCA = 3.14159265358979323846f / RCA;

    // ---- candidate neighbor j = lane ----
    const float cix = s_cx[i], ciy = s_cy[i], ciz = s_cz[i];
    const bool  valid_i = (s_sp[i] >= 0);

    float vx = s_cx[lane] - cix;
    float vy = s_cy[lane] - ciy;
    float vz = s_cz[lane] - ciz;
    float d2 = vx*vx + vy*vy + vz*vz;
    float inv = rsqrt_apx(fmaxf(d2, 1e-24f));
    float d   = d2 * inv;
    int   spl = s_sp[lane];
    int   spc = min(max(spl, 0), NSP-1);
    bool  pair_ok = valid_i && (spl >= 0) && (lane != i);

    // ---- radial: 4 shifts per warp, staggered shared atomics ----
    if (pair_ok && d <= RCR) {
        float fcR  = fmaf(0.5f, __cosf(d * PI_RCR), 0.5f);
        float base = 0.25f * fcR;
        float* rad = &s_acc[w][spc * NSHFR];
        int r0 = lane & 15;
        #pragma unroll
        for (int k = w*4; k < w*4 + 4; k++) {
            int r = (r0 + k) & 15;
            float e = d - s_shfR[r];
            atomicAdd(&rad[r], base * ex2f(nEtaR * (e * e)));
        }
    }

    // ---- neighbor list: species-sorted compaction (warp 0 writes it) ----
    bool isnb = pair_ok && (d <= RCA);
    unsigned ms[NSP];
    #pragma unroll
    for (int s = 0; s < NSP; s++)
        ms[s] = __ballot_sync(0xffffffffu, isnb && (spc == s));

    int o1 = __popc(ms[0]);
    int o2 = o1 + __popc(ms[1]);
    int o3 = o2 + __popc(ms[2]);
    int ncA = o3 + __popc(ms[3]);

    if (w == 0 && isnb) {
        unsigned lt = (1u << lane) - 1u;
        int base = (spc == 0) ? 0 : (spc == 1) ? o1 : (spc == 2) ? o2 : o3;
        int pos = base + __popc(ms[spc] & lt);
        float fcA = fmaf(0.5f, __cosf(d * PI_RCA), 0.5f);
        float us  = inv * SQRT095;
        s_n4[pos]  = make_float4(vx*us, vy*us, vz*us, 0.5f*d);
        s_nlg[pos] = lg2f(fcA);
        s_nsp[pos] = spc;
    }

    // ---- closed-form bin counts & even-padded offsets (all threads) ----
    const int n0 = o1, n1 = o2-o1, n2 = o3-o2, n3 = ncA-o3;
    int cnt[NPAIRBIN];
    cnt[0] = (n0*(n0-1))>>1; cnt[1] = n0*n1; cnt[2] = n0*n2; cnt[3] = n0*n3;
    cnt[4] = (n1*(n1-1))>>1; cnt[5] = n1*n2; cnt[6] = n1*n3;
    cnt[7] = (n2*(n2-1))>>1; cnt[8] = n2*n3;
    cnt[9] = (n3*(n3-1))>>1;
    int off[NPAIRBIN+1];
    off[0] = 0;
    #pragma unroll
    for (int bb = 0; bb < NPAIRBIN; bb++) off[bb+1] = off[bb] + ((cnt[bb]+1) & ~1);
    const int Ptot = off[NPAIRBIN];

    if (tid < NPAIRBIN) s_pos[tid] = off[tid];
    // pad records (position independent of atomics)
    if (tid < NPAIRBIN && (cnt[tid] & 1)) {
        int s = off[tid] + cnt[tid];
        s_c[s] = 0.0f; s_s[s] = 0.0f; s_A[s] = -1e30f; s_B[s] = 0.0f;
    }
    __syncthreads();

    // ---- geometry phase: one lane per pair, flat triangular enumeration ----
    const int P = (ncA * (ncA - 1)) >> 1;
    const float zoff = z32 ? -31.0f : 1.0f;   // lg2(2*fa*fb)=1+..., minus 32 if folded pow
    const float nEtaA2m = -2.0f * nEtaA;
    {
        const float fn1 = (float)(2*ncA - 1);
        for (int g = tid; g < P; g += AWARPS*32) {
            float sdisc = sqrtf(fmaf(fn1, fn1, (float)(-8*g)));
            int a = (int)(0.5f * (fn1 - sdisc));
            a = max(a, 0);
            while (a*(ncA-1) - ((a*(a-1))>>1) > g) a--;
            while ((a+1)*(ncA-1) - (((a+1)*a)>>1) <= g) a++;
            int q = g - (a*(ncA-1) - ((a*(a-1))>>1)) + a + 1;

            float4 A4 = s_n4[a];
            float4 B4 = s_n4[q];
            float c  = A4.x*B4.x + A4.y*B4.y + A4.z*B4.z;   // 0.95*cos(theta)
            float st = sqrt_apx(fmaf(-c, c, 1.0f));          // 0.95*sin >= 0
            float dm = A4.w + B4.w;                          // dmean
            float lg = s_nlg[a] + s_nlg[q] + zoff;
            int sa = s_nsp[a], sq = s_nsp[q];
            int lo = min(sa, sq), hi = max(sa, sq);
            int pbin = lo*NSP - ((lo*(lo-1))>>1) + (hi - lo);
            int slot = atomicAdd(&s_pos[pbin], 1);
            s_c[slot] = c;
            s_s[slot] = st;
            s_A[slot] = fmaf(nEtaA * dm, dm, lg);
            s_B[slot] = nEtaA2m * dm;
        }
    }
    __syncthreads();

    // ---- broadcast phase: warp w sweeps its (even-aligned) quarter ----
    const float shfA_l = s_shfA[lane >> 3];
    const float cZ = s_cosZ[lane & 7];
    const float sZ = s_sinZ[lane & 7];
    const float Cl = nEtaA * shfA_l * shfA_l;
    float* accA = &s_acc[w][RAD_FEAT];

    int g0 = ((Ptot * w) >> 2) & ~1;
    int g1 = (w == 3) ? Ptot : (((Ptot * (w+1)) >> 2) & ~1);

    if (z32) {
        const ull cZ2 = pk2(cZ, cZ), sZ2 = pk2(sZ, sZ);
        const ull shfA2 = pk2(shfA_l, shfA_l), Cl2 = pk2(Cl, Cl);
        const ull one2 = pk2(1.0f, 1.0f);
        #pragma unroll 1
        for (int bin = 0; bin < NPAIRBIN; bin++) {
            int lo = max(off[bin], g0), hi = min(off[bin+1], g1);
            if (lo >= hi) continue;
            ull r2 = 0;
            #pragma unroll 2
            for (int g = lo; g < hi; g += 2) {
                ull c2 = *(const ull*)&s_c[g];   // LDS.64 broadcast
                ull s2 = *(const ull*)&s_s[g];
                ull A2 = *(const ull*)&s_A[g];
                ull B2 = *(const ull*)&s_B[g];
                ull t2 = fma2(s2, sZ2, one2);
                ull y  = fma2(c2, cZ2, t2);        // 1 + cos(theta - ShfZ)
                ull y2_ = mul2(y, y);
                ull y4 = mul2(y2_, y2_);
                ull y8 = mul2(y4, y4);
                ull y16 = mul2(y8, y8);
                ull y32 = mul2(y16, y16);
                ull arg = add2(fma2(B2, shfA2, A2), Cl2);
                float alo, ahi; upk2(arg, alo, ahi);
                ull e2 = pk2(ex2f(alo), ex2f(ahi));
                r2 = fma2(y32, e2, r2);
            }
            float rlo, rhi; upk2(r2, rlo, rhi);
            accA[bin*32 + lane] += rlo + rhi;
        }
    } else {
        #pragma unroll 1
        for (int bin = 0; bin < NPAIRBIN; bin++) {
            int lo = max(off[bin], g0), hi = min(off[bin+1], g1);
            if (lo >= hi) continue;
            float r = 0.0f;
            for (int g = lo; g < hi; g++) {
                float t = fmaf(s_s[g], sZ, 1.0f);
                float y = fmaf(s_c[g], cZ, t);
                float f1 = __powf(0.5f * y, zeta);
                float arg = fmaf(s_B[g], shfA_l, s_A[g]) + Cl;
                r = fmaf(f1, ex2f(arg), r);
            }
            accA[bin*32 + lane] += r;
        }
    }
    __syncthreads();

    // ---- write: sum the 4 warp banks; each warp writes a quarter ----
    float* op = out + (size_t)(b*NATOMS + i) * OUT_FEAT;
    #pragma unroll
    for (int f = w*96 + lane; f < w*96 + 96; f += 32)
        op[f] = (s_acc[0][f] + s_acc[1][f]) + (s_acc[2][f] + s_acc[3][f]);
}

extern "C" void kernel_launch(void* const* d_in, const int* in_sizes, int n_in,
                              void* d_out, int out_size)
{
    const float* coords = (const float*)d_in[0];
    const float* etaR   = (const float*)d_in[1];
    const float* shfR   = (const float*)d_in[2];
    const float* etaA   = (const float*)d_in[3];
    const float* zeta   = (const float*)d_in[4];
    const float* shfA   = (const float*)d_in[5];
    const float* shfZ   = (const float*)d_in[6];
    const int*   spec   = (const int*)d_in[7];
    float* out = (float*)d_out;

    int B = in_sizes[0] / (NATOMS*3);
    dim3 grid(B * NATOMS);   // 1 atom per block, 4 warps
    aev_kernel<<<grid, AWARPS*32>>>(coords, etaR, shfR, etaA, zeta, shfA, shfZ, spec, out);
}

// round 8
// speedup vs baseline: 1.1747x; 1.1747x over previous
#include <cuda_runtime.h>
#include <math.h>

#define RCR 5.2f
#define RCA 3.5f
#define NSP 4
#define NATOMS 32
#define NSHFR 16
#define NSHFA 4
#define NSHFZ 8
#define NPAIRBIN 10
#define RAD_FEAT (NSP*NSHFR)            /* 64  */
#define ANG_FEAT (NPAIRBIN*NSHFA*NSHFZ) /* 320 */
#define OUT_FEAT (RAD_FEAT+ANG_FEAT)    /* 384 */
#define AWARPS 4
#define MAXP 480                         /* 31*30/2=465 + <=10 pads, even */
#define LOG2E 1.4426950408889634f
#define SQRT095 0.97467943448089633f

typedef unsigned long long ull;

__device__ __forceinline__ float ex2f(float x){ float y; asm("ex2.approx.ftz.f32 %0, %1;":"=f"(y):"f"(x)); return y; }
__device__ __forceinline__ float lg2f(float x){ float y; asm("lg2.approx.ftz.f32 %0, %1;":"=f"(y):"f"(x)); return y; }
__device__ __forceinline__ float sqrt_apx(float x){ float y; asm("sqrt.approx.ftz.f32 %0, %1;":"=f"(y):"f"(x)); return y; }
__device__ __forceinline__ float rsqrt_apx(float x){ float y; asm("rsqrt.approx.ftz.f32 %0, %1;":"=f"(y):"f"(x)); return y; }

__device__ __forceinline__ ull pk2(float lo, float hi){ ull r; asm("mov.b64 %0,{%1,%2};":"=l"(r):"f"(lo),"f"(hi)); return r; }
__device__ __forceinline__ void upk2(ull v, float& lo, float& hi){ asm("mov.b64 {%0,%1},%2;":"=f"(lo),"=f"(hi):"l"(v)); }
__device__ __forceinline__ ull fma2(ull a, ull b, ull c){ ull d; asm("fma.rn.f32x2 %0,%1,%2,%3;":"=l"(d):"l"(a),"l"(b),"l"(c)); return d; }
__device__ __forceinline__ ull mul2(ull a, ull b){ ull d; asm("mul.rn.f32x2 %0,%1,%2;":"=l"(d):"l"(a),"l"(b)); return d; }
__device__ __forceinline__ ull add2(ull a, ull b){ ull d; asm("add.rn.f32x2 %0,%1,%2;":"=l"(d):"l"(a),"l"(b)); return d; }

__global__ __launch_bounds__(AWARPS*32) void aev_kernel(
    const float* __restrict__ coords,
    const float* __restrict__ etaR_p,
    const float* __restrict__ shfR_p,
    const float* __restrict__ etaA_p,
    const float* __restrict__ zeta_p,
    const float* __restrict__ shfA_p,
    const float* __restrict__ shfZ_p,
    const int*   __restrict__ species,
    float* __restrict__ out)
{
    __shared__ float s_cx[NATOMS], s_cy[NATOMS], s_cz[NATOMS];
    __shared__ int   s_sp[NATOMS];
    __shared__ float s_shfR[NSHFR], s_shfA[NSHFA];
    __shared__ float s_cosZ[NSHFZ], s_sinZ[NSHFZ];
    __shared__ float4 s_n4[NATOMS];          // ux,uy,uz (x sqrt095), 0.5*d
    __shared__ float  s_nlg[NATOMS];         // lg2(fcA)
    __shared__ int    s_nsp[NATOMS];         // species
    __shared__ __align__(8) float s_c [MAXP];   // SoA pair records (bin-sorted)
    __shared__ __align__(8) float s_s [MAXP];
    __shared__ __align__(8) float s_A [MAXP];
    __shared__ __align__(8) float s_B [MAXP];
    __shared__ int    s_pos[NPAIRBIN];       // fill cursors
    __shared__ float  s_acc[AWARPS][OUT_FEAT];
    __shared__ float  s_etaR, s_etaA, s_zeta;

    const int tid  = threadIdx.x;
    const int w    = tid >> 5;
    const int lane = tid & 31;
    const int b    = blockIdx.x >> 5;        // 32 blocks per molecule
    const int i    = blockIdx.x & 31;        // this block's atom

    // ---- block-wide loads ----
    if (tid < NATOMS) {
        s_cx[tid] = coords[(b*NATOMS + tid)*3 + 0];
        s_cy[tid] = coords[(b*NATOMS + tid)*3 + 1];
        s_cz[tid] = coords[(b*NATOMS + tid)*3 + 2];
        s_sp[tid] = species[b*NATOMS + tid];
    } else if (tid < 32 + NSHFR) {
        s_shfR[tid-32] = shfR_p[tid-32];
    } else if (tid < 48 + NSHFA) {
        s_shfA[tid-48] = shfA_p[tid-48];
    } else if (tid < 55) {
        if (tid == 52) s_etaR = etaR_p[0];
        if (tid == 53) s_etaA = etaA_p[0];
        if (tid == 54) s_zeta = zeta_p[0];
    } else if (tid >= 56 && tid < 64) {
        float z = shfZ_p[tid-56];
        s_cosZ[tid-56] = cosf(z);
        s_sinZ[tid-56] = sinf(z);
    }
    for (int f = tid; f < AWARPS*OUT_FEAT; f += blockDim.x)
        (&s_acc[0][0])[f] = 0.0f;
    __syncthreads();

    const float zeta = s_zeta;
    const float nEtaR = -s_etaR * LOG2E;
    const float nEtaA = -s_etaA * LOG2E;
    const bool  z32   = (fabsf(zeta - 32.0f) < 1e-4f);
    const float PI_RCR = 3.14159265358979323846f / RCR;
    const float PI_RCA = 3.14159265358979323846f / RCA;

    // ---- candidate neighbor j = lane ----
    const float cix = s_cx[i], ciy = s_cy[i], ciz = s_cz[i];
    const bool  valid_i = (s_sp[i] >= 0);

    float vx = s_cx[lane] - cix;
    float vy = s_cy[lane] - ciy;
    float vz = s_cz[lane] - ciz;
    float d2 = vx*vx + vy*vy + vz*vz;
    float inv = rsqrt_apx(fmaxf(d2, 1e-24f));
    float d   = d2 * inv;
    int   spl = s_sp[lane];
    int   spc = min(max(spl, 0), NSP-1);
    bool  pair_ok = valid_i && (spl >= 0) && (lane != i);

    // ---- radial: 4 shifts per warp, staggered shared atomics ----
    if (pair_ok && d <= RCR) {
        float fcR  = fmaf(0.5f, __cosf(d * PI_RCR), 0.5f);
        float base = 0.25f * fcR;
        float* rad = &s_acc[w][spc * NSHFR];
        int r0 = lane & 15;
        #pragma unroll
        for (int k = w*4; k < w*4 + 4; k++) {
            int r = (r0 + k) & 15;
            float e = d - s_shfR[r];
            atomicAdd(&rad[r], base * ex2f(nEtaR * (e * e)));
        }
    }

    // ---- neighbor list: species-sorted compaction (warp 0 writes it) ----
    bool isnb = pair_ok && (d <= RCA);
    unsigned ms[NSP];
    #pragma unroll
    for (int s = 0; s < NSP; s++)
        ms[s] = __ballot_sync(0xffffffffu, isnb && (spc == s));

    int o1 = __popc(ms[0]);
    int o2 = o1 + __popc(ms[1]);
    int o3 = o2 + __popc(ms[2]);
    int ncA = o3 + __popc(ms[3]);

    if (w == 0 && isnb) {
        unsigned lt = (1u << lane) - 1u;
        int base = (spc == 0) ? 0 : (spc == 1) ? o1 : (spc == 2) ? o2 : o3;
        int pos = base + __popc(ms[spc] & lt);
        float fcA = fmaf(0.5f, __cosf(d * PI_RCA), 0.5f);
        float us  = inv * SQRT095;
        s_n4[pos]  = make_float4(vx*us, vy*us, vz*us, 0.5f*d);
        s_nlg[pos] = lg2f(fcA);
        s_nsp[pos] = spc;
    }

    // ---- closed-form bin counts & even-padded offsets (registers only) ----
    const int n0 = o1, n1 = o2-o1, n2 = o3-o2, n3 = ncA-o3;
    int cnt[NPAIRBIN];
    cnt[0] = (n0*(n0-1))>>1; cnt[1] = n0*n1; cnt[2] = n0*n2; cnt[3] = n0*n3;
    cnt[4] = (n1*(n1-1))>>1; cnt[5] = n1*n2; cnt[6] = n1*n3;
    cnt[7] = (n2*(n2-1))>>1; cnt[8] = n2*n3;
    cnt[9] = (n3*(n3-1))>>1;
    int off[NPAIRBIN+1];
    off[0] = 0;
    #pragma unroll
    for (int bb = 0; bb < NPAIRBIN; bb++) off[bb+1] = off[bb] + ((cnt[bb]+1) & ~1);
    const int Ptot = off[NPAIRBIN];

    if (tid < NPAIRBIN) {
        // constant-indexed selection to avoid any local-mem access
        int offv = 0, cv = 0;
        #pragma unroll
        for (int bb = 0; bb < NPAIRBIN; bb++)
            if (tid == bb) { offv = off[bb]; cv = cnt[bb]; }
        s_pos[tid] = offv;
        if (cv & 1) {   // pad record so every bin length is even
            int s = offv + cv;
            s_c[s] = 0.0f; s_s[s] = 0.0f; s_A[s] = -1e30f; s_B[s] = 0.0f;
        }
    }
    __syncthreads();

    // ---- geometry phase: one lane per pair, flat triangular enumeration ----
    const int P = (ncA * (ncA - 1)) >> 1;
    const float zoff = z32 ? -31.0f : 1.0f;   // lg2(2*fa*fb)=1+..., minus 32 if folded pow
    const float nEtaA2m = -2.0f * nEtaA;
    {
        const float fn1 = (float)(2*ncA - 1);
        for (int g = tid; g < P; g += AWARPS*32) {
            float sdisc = sqrtf(fmaf(fn1, fn1, (float)(-8*g)));
            int a = (int)(0.5f * (fn1 - sdisc));
            a = max(a, 0);
            while (a*(ncA-1) - ((a*(a-1))>>1) > g) a--;
            while ((a+1)*(ncA-1) - (((a+1)*a)>>1) <= g) a++;
            int q = g - (a*(ncA-1) - ((a*(a-1))>>1)) + a + 1;

            float4 A4 = s_n4[a];
            float4 B4 = s_n4[q];
            float c  = A4.x*B4.x + A4.y*B4.y + A4.z*B4.z;   // 0.95*cos(theta)
            float st = sqrt_apx(fmaf(-c, c, 1.0f));          // 0.95*sin >= 0
            float dm = A4.w + B4.w;                          // dmean
            float lg = s_nlg[a] + s_nlg[q] + zoff;
            int sa = s_nsp[a], sq = s_nsp[q];
            int lo = min(sa, sq), hi = max(sa, sq);
            int pbin = lo*NSP - ((lo*(lo-1))>>1) + (hi - lo);
            int slot = atomicAdd(&s_pos[pbin], 1);
            s_c[slot] = c;
            s_s[slot] = st;
            s_A[slot] = fmaf(nEtaA * dm, dm, lg);
            s_B[slot] = nEtaA2m * dm;
        }
    }
    __syncthreads();

    // ---- broadcast phase: warp w sweeps its (even-aligned) quarter ----
    const float shfA_l = s_shfA[lane >> 3];
    const float cZ = s_cosZ[lane & 7];
    const float sZ = s_sinZ[lane & 7];
    const float Cl = nEtaA * shfA_l * shfA_l;
    float* accA = &s_acc[w][RAD_FEAT];

    int g0 = ((Ptot * w) >> 2) & ~1;
    int g1 = (w == 3) ? Ptot : (((Ptot * (w+1)) >> 2) & ~1);

    if (z32) {
        const ull cZ2 = pk2(cZ, cZ), sZ2 = pk2(sZ, sZ);
        const ull shfA2 = pk2(shfA_l, shfA_l), Cl2 = pk2(Cl, Cl);
        const ull one2 = pk2(1.0f, 1.0f);
        #pragma unroll
        for (int bin = 0; bin < NPAIRBIN; bin++) {      // FULL unroll: off[] stays in regs
            int lo = max(off[bin], g0), hi = min(off[bin+1], g1);
            if (lo >= hi) continue;
            ull r2 = 0;
            #pragma unroll 2
            for (int g = lo; g < hi; g += 2) {
                ull c2 = *(const ull*)&s_c[g];   // LDS.64 broadcast
                ull s2 = *(const ull*)&s_s[g];
                ull A2 = *(const ull*)&s_A[g];
                ull B2 = *(const ull*)&s_B[g];
                ull t2 = fma2(s2, sZ2, one2);
                ull y  = fma2(c2, cZ2, t2);        // 1 + cos(theta - ShfZ)
                ull y2_ = mul2(y, y);
                ull y4 = mul2(y2_, y2_);
                ull y8 = mul2(y4, y4);
                ull y16 = mul2(y8, y8);
                ull y32 = mul2(y16, y16);
                ull arg = add2(fma2(B2, shfA2, A2), Cl2);
                float alo, ahi; upk2(arg, alo, ahi);
                ull e2 = pk2(ex2f(alo), ex2f(ahi));
                r2 = fma2(y32, e2, r2);
            }
            float rlo, rhi; upk2(r2, rlo, rhi);
            accA[bin*32 + lane] += rlo + rhi;
        }
    } else {
        #pragma unroll
        for (int bin = 0; bin < NPAIRBIN; bin++) {
            int lo = max(off[bin], g0), hi = min(off[bin+1], g1);
            if (lo >= hi) continue;
            float r = 0.0f;
            for (int g = lo; g < hi; g++) {
                float t = fmaf(s_s[g], sZ, 1.0f);
                float y = fmaf(s_c[g], cZ, t);
                float f1 = __powf(0.5f * y, zeta);
                float arg = fmaf(s_B[g], shfA_l, s_A[g]) + Cl;
                r = fmaf(f1, ex2f(arg), r);
            }
            accA[bin*32 + lane] += r;
        }
    }
    __syncthreads();

    // ---- write: sum the 4 warp banks; each warp writes a quarter ----
    float* op = out + (size_t)(b*NATOMS + i) * OUT_FEAT;
    #pragma unroll
    for (int f = w*96 + lane; f < w*96 + 96; f += 32)
        op[f] = (s_acc[0][f] + s_acc[1][f]) + (s_acc[2][f] + s_acc[3][f]);
}

extern "C" void kernel_launch(void* const* d_in, const int* in_sizes, int n_in,
                              void* d_out, int out_size)
{
    const float* coords = (const float*)d_in[0];
    const float* etaR   = (const float*)d_in[1];
    const float* shfR   = (const float*)d_in[2];
    const float* etaA   = (const float*)d_in[3];
    const float* zeta   = (const float*)d_in[4];
    const float* shfA   = (const float*)d_in[5];
    const float* shfZ   = (const float*)d_in[6];
    const int*   spec   = (const int*)d_in[7];
    float* out = (float*)d_out;

    int B = in_sizes[0] / (NATOMS*3);
    dim3 grid(B * NATOMS);   // 1 atom per block, 4 warps
    aev_kernel<<<grid, AWARPS*32>>>(coords, etaR, shfR, etaA, zeta, shfA, shfZ, spec, out);
}

// round 9
// speedup vs baseline: 1.1878x; 1.0111x over previous
#include <cuda_runtime.h>
#include <math.h>

#define RCR 5.2f
#define RCA 3.5f
#define NSP 4
#define NATOMS 32
#define NSHFR 16
#define NSHFA 4
#define NSHFZ 8
#define NPAIRBIN 10
#define RAD_FEAT (NSP*NSHFR)            /* 64  */
#define ANG_FEAT (NPAIRBIN*NSHFA*NSHFZ) /* 320 */
#define OUT_FEAT (RAD_FEAT+ANG_FEAT)    /* 384 */
#define AWARPS 4
#define MAXP 480                         /* 31*30/2=465 + <=10 pads, even */
#define LOG2E 1.4426950408889634f
#define SQRT095 0.97467943448089633f

typedef unsigned long long ull;

__device__ __forceinline__ float ex2f(float x){ float y; asm("ex2.approx.ftz.f32 %0, %1;":"=f"(y):"f"(x)); return y; }
__device__ __forceinline__ float lg2f(float x){ float y; asm("lg2.approx.ftz.f32 %0, %1;":"=f"(y):"f"(x)); return y; }
__device__ __forceinline__ float sqrt_apx(float x){ float y; asm("sqrt.approx.ftz.f32 %0, %1;":"=f"(y):"f"(x)); return y; }
__device__ __forceinline__ float rsqrt_apx(float x){ float y; asm("rsqrt.approx.ftz.f32 %0, %1;":"=f"(y):"f"(x)); return y; }

__device__ __forceinline__ ull pk2(float lo, float hi){ ull r; asm("mov.b64 %0,{%1,%2};":"=l"(r):"f"(lo),"f"(hi)); return r; }
__device__ __forceinline__ void upk2(ull v, float& lo, float& hi){ asm("mov.b64 {%0,%1},%2;":"=f"(lo),"=f"(hi):"l"(v)); }
__device__ __forceinline__ ull fma2(ull a, ull b, ull c){ ull d; asm("fma.rn.f32x2 %0,%1,%2,%3;":"=l"(d):"l"(a),"l"(b),"l"(c)); return d; }
__device__ __forceinline__ ull mul2(ull a, ull b){ ull d; asm("mul.rn.f32x2 %0,%1,%2;":"=l"(d):"l"(a),"l"(b)); return d; }
__device__ __forceinline__ ull add2(ull a, ull b){ ull d; asm("add.rn.f32x2 %0,%1,%2;":"=l"(d):"l"(a),"l"(b)); return d; }

__global__ __launch_bounds__(AWARPS*32) void aev_kernel(
    const float* __restrict__ coords,
    const float* __restrict__ etaR_p,
    const float* __restrict__ shfR_p,
    const float* __restrict__ etaA_p,
    const float* __restrict__ zeta_p,
    const float* __restrict__ shfA_p,
    const float* __restrict__ shfZ_p,
    const int*   __restrict__ species,
    float* __restrict__ out)
{
    __shared__ float s_cx[NATOMS], s_cy[NATOMS], s_cz[NATOMS];
    __shared__ int   s_sp[NATOMS];
    __shared__ float s_shfR[NSHFR], s_shfA[NSHFA];
    __shared__ float s_cosZ[NSHFZ], s_sinZ[NSHFZ];
    __shared__ float4 s_n4[NATOMS];          // ux,uy,uz (x sqrt095), 0.5*d
    __shared__ float  s_nlg[NATOMS];         // lg2(fcA)
    __shared__ int    s_nsp[NATOMS];         // species
    __shared__ __align__(16) float4 s_r0[MAXP/2];  // (c0,c1,st0,st1) per 2 pairs
    __shared__ __align__(16) float4 s_r1[MAXP/2];  // (A0,A1,B0,B1)  per 2 pairs
    __shared__ int    s_pos[NPAIRBIN];       // fill cursors
    __shared__ __align__(16) float s_accA[ANG_FEAT];       // single angular bank
    __shared__ __align__(16) float s_accR[AWARPS][RAD_FEAT]; // per-warp radial banks
    __shared__ float  s_etaR, s_etaA, s_zeta;

    const int tid  = threadIdx.x;
    const int w    = tid >> 5;
    const int lane = tid & 31;
    const int b    = blockIdx.x >> 5;        // 32 blocks per molecule
    const int i    = blockIdx.x & 31;        // this block's atom

    // ---- block-wide loads ----
    if (tid < NATOMS) {
        s_cx[tid] = coords[(b*NATOMS + tid)*3 + 0];
        s_cy[tid] = coords[(b*NATOMS + tid)*3 + 1];
        s_cz[tid] = coords[(b*NATOMS + tid)*3 + 2];
        s_sp[tid] = species[b*NATOMS + tid];
    } else if (tid < 32 + NSHFR) {
        s_shfR[tid-32] = shfR_p[tid-32];
    } else if (tid < 48 + NSHFA) {
        s_shfA[tid-48] = shfA_p[tid-48];
    } else if (tid < 55) {
        if (tid == 52) s_etaR = etaR_p[0];
        if (tid == 53) s_etaA = etaA_p[0];
        if (tid == 54) s_zeta = zeta_p[0];
    } else if (tid >= 56 && tid < 64) {
        float z = shfZ_p[tid-56];
        s_cosZ[tid-56] = cosf(z);
        s_sinZ[tid-56] = sinf(z);
    }
    // zero accumulators with float4 stores (one pass)
    {
        float4 zz = make_float4(0.f, 0.f, 0.f, 0.f);
        float4* za = (float4*)s_accA;              // 80 float4
        float4* zr = (float4*)&s_accR[0][0];       // 64 float4
        if (tid < 80) za[tid] = zz;
        if (tid < 64) zr[tid] = zz;
    }
    __syncthreads();

    const float zeta = s_zeta;
    const float nEtaR = -s_etaR * LOG2E;
    const float nEtaA = -s_etaA * LOG2E;
    const bool  z32   = (fabsf(zeta - 32.0f) < 1e-4f);
    const float PI_RCR = 3.14159265358979323846f / RCR;
    const float PI_RCA = 3.14159265358979323846f / RCA;

    // ---- candidate neighbor j = lane ----
    const float cix = s_cx[i], ciy = s_cy[i], ciz = s_cz[i];
    const bool  valid_i = (s_sp[i] >= 0);

    float vx = s_cx[lane] - cix;
    float vy = s_cy[lane] - ciy;
    float vz = s_cz[lane] - ciz;
    float d2 = vx*vx + vy*vy + vz*vz;
    float inv = rsqrt_apx(fmaxf(d2, 1e-24f));
    float d   = d2 * inv;
    int   spl = s_sp[lane];
    int   spc = min(max(spl, 0), NSP-1);
    bool  pair_ok = valid_i && (spl >= 0) && (lane != i);

    // ---- radial: 4 shifts per warp, staggered shared atomics ----
    if (pair_ok && d <= RCR) {
        float fcR  = fmaf(0.5f, __cosf(d * PI_RCR), 0.5f);
        float base = 0.25f * fcR;
        float* rad = &s_accR[w][spc * NSHFR];
        int r0 = lane & 15;
        #pragma unroll
        for (int k = w*4; k < w*4 + 4; k++) {
            int r = (r0 + k) & 15;
            float e = d - s_shfR[r];
            atomicAdd(&rad[r], base * ex2f(nEtaR * (e * e)));
        }
    }

    // ---- neighbor list: species-sorted compaction (warp 0 writes it) ----
    bool isnb = pair_ok && (d <= RCA);
    unsigned ms[NSP];
    #pragma unroll
    for (int s = 0; s < NSP; s++)
        ms[s] = __ballot_sync(0xffffffffu, isnb && (spc == s));

    int o1 = __popc(ms[0]);
    int o2 = o1 + __popc(ms[1]);
    int o3 = o2 + __popc(ms[2]);
    int ncA = o3 + __popc(ms[3]);

    if (w == 0 && isnb) {
        unsigned lt = (1u << lane) - 1u;
        int base = (spc == 0) ? 0 : (spc == 1) ? o1 : (spc == 2) ? o2 : o3;
        int pos = base + __popc(ms[spc] & lt);
        float fcA = fmaf(0.5f, __cosf(d * PI_RCA), 0.5f);
        float us  = inv * SQRT095;
        s_n4[pos]  = make_float4(vx*us, vy*us, vz*us, 0.5f*d);
        s_nlg[pos] = lg2f(fcA);
        s_nsp[pos] = spc;
    }

    // ---- closed-form bin counts & even-padded offsets (registers only) ----
    const int n0 = o1, n1 = o2-o1, n2 = o3-o2, n3 = ncA-o3;
    int cnt[NPAIRBIN];
    cnt[0] = (n0*(n0-1))>>1; cnt[1] = n0*n1; cnt[2] = n0*n2; cnt[3] = n0*n3;
    cnt[4] = (n1*(n1-1))>>1; cnt[5] = n1*n2; cnt[6] = n1*n3;
    cnt[7] = (n2*(n2-1))>>1; cnt[8] = n2*n3;
    cnt[9] = (n3*(n3-1))>>1;
    int off[NPAIRBIN+1];
    off[0] = 0;
    #pragma unroll
    for (int bb = 0; bb < NPAIRBIN; bb++) off[bb+1] = off[bb] + ((cnt[bb]+1) & ~1);
    const int Ptot = off[NPAIRBIN];

    if (tid < NPAIRBIN) {
        int offv = 0, cv = 0;
        #pragma unroll
        for (int bb = 0; bb < NPAIRBIN; bb++)
            if (tid == bb) { offv = off[bb]; cv = cnt[bb]; }
        s_pos[tid] = offv;
        if (cv & 1) {   // pad record: zero contribution (ex2(-1e30)->0)
            int s = offv + cv, k = s >> 1, h = s & 1;
            float* r0p = (float*)&s_r0[k];
            float* r1p = (float*)&s_r1[k];
            r0p[h] = 0.0f; r0p[2+h] = 0.0f;
            r1p[h] = -1e30f; r1p[2+h] = 0.0f;
        }
    }
    __syncthreads();

    // ---- geometry phase: one lane per pair, flat triangular enumeration ----
    const int P = (ncA * (ncA - 1)) >> 1;
    const float zoff = z32 ? -31.0f : 1.0f;
    const float nEtaA2m = -2.0f * nEtaA;
    {
        const float fn1 = (float)(2*ncA - 1);
        for (int g = tid; g < P; g += AWARPS*32) {
            float sdisc = sqrtf(fmaf(fn1, fn1, (float)(-8*g)));
            int a = (int)(0.5f * (fn1 - sdisc));
            a = max(a, 0);
            while (a*(ncA-1) - ((a*(a-1))>>1) > g) a--;
            while ((a+1)*(ncA-1) - (((a+1)*a)>>1) <= g) a++;
            int q = g - (a*(ncA-1) - ((a*(a-1))>>1)) + a + 1;

            float4 A4 = s_n4[a];
            float4 B4 = s_n4[q];
            float c  = A4.x*B4.x + A4.y*B4.y + A4.z*B4.z;   // 0.95*cos(theta)
            float st = sqrt_apx(fmaf(-c, c, 1.0f));
            float dm = A4.w + B4.w;
            float lg = s_nlg[a] + s_nlg[q] + zoff;
            int sa = s_nsp[a], sq = s_nsp[q];
            int lo = min(sa, sq), hi = max(sa, sq);
            int pbin = lo*NSP - ((lo*(lo-1))>>1) + (hi - lo);
            int slot = atomicAdd(&s_pos[pbin], 1);
            int k = slot >> 1, h = slot & 1;
            float* r0p = (float*)&s_r0[k];
            float* r1p = (float*)&s_r1[k];
            r0p[h]   = c;
            r0p[2+h] = st;
            r1p[h]   = fmaf(nEtaA * dm, dm, lg);
            r1p[2+h] = nEtaA2m * dm;
        }
    }
    __syncthreads();

    // ---- broadcast phase: warp w sweeps its (even-aligned) quarter ----
    const float shfA_l = s_shfA[lane >> 3];
    const float cZ = s_cosZ[lane & 7];
    const float sZ = s_sinZ[lane & 7];
    const float Cl = nEtaA * shfA_l * shfA_l;

    int g0 = ((Ptot * w) >> 2) & ~1;
    int g1 = (w == 3) ? Ptot : (((Ptot * (w+1)) >> 2) & ~1);

    if (z32) {
        const ull cZ2 = pk2(cZ, cZ), sZ2 = pk2(sZ, sZ);
        const ull shfA2 = pk2(shfA_l, shfA_l), Cl2 = pk2(Cl, Cl);
        const ull one2 = pk2(1.0f, 1.0f);
        #pragma unroll
        for (int bin = 0; bin < NPAIRBIN; bin++) {
            int lo = max(off[bin], g0), hi = min(off[bin+1], g1);
            if (lo >= hi) continue;
            int k0 = lo >> 1, k1 = hi >> 1;
            ull r2 = 0;
            #pragma unroll 4
            for (int k = k0; k < k1; k++) {
                float4 R0 = s_r0[k];              // LDS.128
                float4 R1 = s_r1[k];              // LDS.128
                ull c2 = pk2(R0.x, R0.y);
                ull s2 = pk2(R0.z, R0.w);
                ull A2 = pk2(R1.x, R1.y);
                ull B2 = pk2(R1.z, R1.w);
                ull t2 = fma2(s2, sZ2, one2);
                ull y  = fma2(c2, cZ2, t2);        // 1 + cos(theta - ShfZ)
                ull yy2 = mul2(y, y);
                ull y4 = mul2(yy2, yy2);
                ull y8 = mul2(y4, y4);
                ull y16 = mul2(y8, y8);
                ull y32 = mul2(y16, y16);
                ull arg = add2(fma2(B2, shfA2, A2), Cl2);
                float alo, ahi; upk2(arg, alo, ahi);
                ull e2 = pk2(ex2f(alo), ex2f(ahi));
                r2 = fma2(y32, e2, r2);
            }
            float rlo, rhi; upk2(r2, rlo, rhi);
            atomicAdd(&s_accA[bin*32 + lane], rlo + rhi);
        }
    } else {
        const float* r0f = (const float*)s_r0;
        const float* r1f = (const float*)s_r1;
        #pragma unroll
        for (int bin = 0; bin < NPAIRBIN; bin++) {
            int lo = max(off[bin], g0), hi = min(off[bin+1], g1);
            if (lo >= hi) continue;
            float r = 0.0f;
            for (int g = lo; g < hi; g++) {
                int k = g >> 1, h = g & 1;
                float c  = r0f[k*4 + h];
                float st = r0f[k*4 + 2 + h];
                float A  = r1f[k*4 + h];
                float Bv = r1f[k*4 + 2 + h];
                float t = fmaf(st, sZ, 1.0f);
                float y = fmaf(c, cZ, t);
                float f1 = __powf(0.5f * y, zeta);
                float arg = fmaf(Bv, shfA_l, A) + Cl;
                r = fmaf(f1, ex2f(arg), r);
            }
            atomicAdd(&s_accA[bin*32 + lane], r);
        }
    }
    __syncthreads();

    // ---- write 384 features (radial: sum 4 banks; angular: direct) ----
    float* op = out + (size_t)(b*NATOMS + i) * OUT_FEAT;
    #pragma unroll
    for (int f = w*96 + lane; f < w*96 + 96; f += 32) {
        float v;
        if (f < RAD_FEAT)
            v = (s_accR[0][f] + s_accR[1][f]) + (s_accR[2][f] + s_accR[3][f]);
        else
            v = s_accA[f - RAD_FEAT];
        op[f] = v;
    }
}

extern "C" void kernel_launch(void* const* d_in, const int* in_sizes, int n_in,
                              void* d_out, int out_size)
{
    const float* coords = (const float*)d_in[0];
    const float* etaR   = (const float*)d_in[1];
    const float* shfR   = (const float*)d_in[2];
    const float* etaA   = (const float*)d_in[3];
    const float* zeta   = (const float*)d_in[4];
    const float* shfA   = (const float*)d_in[5];
    const float* shfZ   = (const float*)d_in[6];
    const int*   spec   = (const int*)d_in[7];
    float* out = (float*)d_out;

    int B = in_sizes[0] / (NATOMS*3);
    dim3 grid(B * NATOMS);   // 1 atom per block, 4 warps
    aev_kernel<<<grid, AWARPS*32>>>(coords, etaR, shfR, etaA, zeta, shfA, shfZ, spec, out);
}